// round 13
// baseline (speedup 1.0000x reference)
#include <cuda_runtime.h>
#include <math.h>
#include <stdint.h>

#define BSZ 1024
#define NN  100
#define HH  128
#define MTOT (BSZ * NN)   // 102400

// ---------------- scratch (no allocs allowed) ----------------
__device__ float g_h0[(size_t)MTOT * HH];
__device__ float g_e[(size_t)MTOT * 2 * HH];
__device__ float g_inp[(size_t)MTOT * 2 * HH];
__device__ float g_gi[(size_t)MTOT * 3 * HH];
__device__ float g_gh[(size_t)MTOT * 3 * HH];
__device__ float g_hid[(size_t)MTOT * HH];
__device__ float g_star[(size_t)BSZ * HH];
// tf32-rounded weight copies
__device__ float g_wih[3 * HH * 2 * HH];
__device__ float g_whh[3 * HH * HH];
__device__ float g_wein[HH * HH];
__device__ float g_weout[HH * HH];
__device__ float g_whn[HH * 2 * HH];

// ---------------- helpers ----------------
__device__ __forceinline__ float totf(float x) {
    uint32_t u; asm("cvt.rna.tf32.f32 %0, %1;" : "=r"(u) : "f"(x));
    return __uint_as_float(u);
}
__device__ __forceinline__ float sigm(float x) { return 1.f / (1.f + expf(-x)); }

__device__ __forceinline__ void mma8(float c[4], float2 a01, float2 a23, float2 b01) {
    asm volatile(
        "mma.sync.aligned.m16n8k8.row.col.f32.tf32.tf32.f32 "
        "{%0,%1,%2,%3},{%4,%5,%6,%7},{%8,%9},{%0,%1,%2,%3};"
        : "+f"(c[0]), "+f"(c[1]), "+f"(c[2]), "+f"(c[3])
        : "r"(__float_as_uint(a01.x)), "r"(__float_as_uint(a01.y)),
          "r"(__float_as_uint(a23.x)), "r"(__float_as_uint(a23.y)),
          "r"(__float_as_uint(b01.x)), "r"(__float_as_uint(b01.y)));
}

// ---------------- tensor-core tf32 GEMM ----------------
// 256 thr, CTA tile 128x128, warp tile 32x64, BK=16, double buffer, 1 bar/K-step.
// float4-quad SMEM: one LDS.128 = one A fragment / two B fragments.
// A quad (srow=((k>>3)<<2)+(k&3), idx=((m>>4)<<3)+(m&7)):
//   {A[m][k], A[m+8][k], A[m][k+4], A[m+8][k+4]}
// B quad (srow same, idx q=p^((p>>3)&7), p=((n>>4)<<3)+(n&7)):
//   {B[n][k], B[n][k+4], B[n+8][k], B[n+8][k+4]}
// BT path: full-quad staging — warps 0-3 stage A, warps 4-7 stage B; each
// thread owns rows (lo, lo+8) x 8 k  =>  4 LDG.128 + 4 STS.128 per K-step.
template<bool BT, bool GUARD, int EPI, bool SPLITK, bool RND, bool ADJ>
__global__ __launch_bounds__(256, 2)
void tc_gemm(const float* __restrict__ A1, const float* __restrict__ A2,
             long sA, int lda, int ksplit,
             const float* __restrict__ B1, const float* __restrict__ B2, int nsB,
             long sB, int ldb,
             const float* __restrict__ bias1, const float* __restrict__ bias2, int nsb,
             float* __restrict__ C, long sC, int ldc,
             int M, int N, int K)
{
    __shared__ float4 As4[2][8][66];
    __shared__ float4 Bs4[2][8][66];

    const long zsel = ADJ ? (long)(blockIdx.z & 1023) : (long)blockIdx.z;
    const int  half_adj = ADJ ? (int)(blockIdx.z >> 10) : 0;

    A1 += zsel * sA + (ADJ ? half_adj * NN : 0);
    C  += zsel * sC + (ADJ ? half_adj * HH : 0);
    const float* biasp = (ADJ && half_adj) ? bias2 : bias1;

    const int m0 = blockIdx.y * 128, n0 = blockIdx.x * 128;
    const int tid = threadIdx.x;
    const int lane = tid & 31, warp = tid >> 5;
    const int wm = warp >> 1, wn = warp & 1;
    const int g = lane >> 2, tig = lane & 3;

    // ---- BT full-quad staging setup ----
    int st_half = 0, st_idx = 0, st_srow0 = 0, st_kg = 0;
    const float *s_lo1 = nullptr, *s_hi1 = nullptr, *s_lo2 = nullptr, *s_hi2 = nullptr;
    // ---- non-BT (ADJ) staging setup ----
    int a_kg = 0, a_idx = 0, a_half = 0, b_k = 0, b_n8 = 0, bsel = 0;
    const float* pA1 = nullptr;
    const float* Bp  = nullptr;

    if (BT) {
        st_half = tid >> 7;                 // 0 = A, 1 = B
        int u = tid & 127;
        int p = u & 63;
        st_kg = (u >> 6) << 3;              // 0 or 8
        st_srow0 = (st_kg >> 3) << 2;       // 0 or 4
        int lo = ((p >> 3) << 4) + (p & 7); // row with bit3 clear
        if (st_half == 0) {
            st_idx = p;
            s_lo1 = A1 + (long)(m0 + lo) * lda;
            s_hi1 = s_lo1 + 8 * lda;
            if (SPLITK) {
                s_lo2 = A2 + (long)(m0 + lo) * lda;
                s_hi2 = s_lo2 + 8 * lda;
            } else { s_lo2 = s_lo1; s_hi2 = s_hi1; }
        } else {
            st_idx = p ^ ((p >> 3) & 7);
            int gn = n0 + lo;
            s_lo1 = (gn < nsB) ? (B1 + (long)gn * ldb) : (B2 + (long)(gn - nsB) * ldb);
            s_hi1 = (gn + 8 < nsB) ? (B1 + (long)(gn + 8) * ldb)
                                   : (B2 + (long)(gn + 8 - nsB) * ldb);
            s_lo2 = s_lo1; s_hi2 = s_hi1;
        }
    } else {
        int a_row = tid >> 1; a_kg = (tid & 1) << 3;
        pA1 = A1 + (long)(m0 + a_row) * lda + a_kg;
        a_idx  = ((a_row >> 4) << 3) + (a_row & 7);
        a_half = (a_row >> 3) & 1;
        b_k = tid >> 4;
        b_n8 = (tid & 15) << 3;
        Bp = B1 + zsel * sB + (ADJ ? half_adj * HH : 0) + (long)b_k * ldb + n0 + b_n8;
        bsel = (b_n8 >> 3) & 1;
    }

    float acc[2][8][4] = {};
    __align__(16) float vr[16];
    __align__(16) float vb[8];
    const int T = (K + 15) >> 4;

    auto ldg = [&](int k0) {
        if (BT) {
            const float* plo; const float* phi;
            if (SPLITK && st_half == 0 && k0 >= ksplit) {
                plo = s_lo2 + (k0 - ksplit) + st_kg;
                phi = s_hi2 + (k0 - ksplit) + st_kg;
            } else {
                plo = s_lo1 + k0 + st_kg;
                phi = s_hi1 + k0 + st_kg;
            }
            *reinterpret_cast<float4*>(vr)      = *reinterpret_cast<const float4*>(plo);
            *reinterpret_cast<float4*>(vr + 4)  = *reinterpret_cast<const float4*>(plo + 4);
            *reinterpret_cast<float4*>(vr + 8)  = *reinterpret_cast<const float4*>(phi);
            *reinterpret_cast<float4*>(vr + 12) = *reinterpret_cast<const float4*>(phi + 4);
        } else {
            // A (guarded)
            bool rok = (m0 + (tid >> 1)) < M;
            if (rok && (k0 + a_kg + 8) <= K) {
                *reinterpret_cast<float4*>(vr)     = *reinterpret_cast<const float4*>(pA1 + k0);
                *reinterpret_cast<float4*>(vr + 4) = *reinterpret_cast<const float4*>(pA1 + k0 + 4);
            } else {
                #pragma unroll
                for (int j = 0; j < 8; j++)
                    vr[j] = (rok && (k0 + a_kg + j) < K) ? pA1[k0 + j] : 0.f;
            }
            // B (k-major)
            if ((k0 + b_k) < K) {
                const float* bp = Bp + (long)k0 * ldb;
                *reinterpret_cast<float4*>(vb)     = *reinterpret_cast<const float4*>(bp);
                *reinterpret_cast<float4*>(vb + 4) = *reinterpret_cast<const float4*>(bp + 4);
            } else {
                #pragma unroll
                for (int j = 0; j < 8; j++) vb[j] = 0.f;
            }
        }
    };

    auto sts = [&](int s) {
        if (BT) {
            float4* base = st_half == 0 ? &As4[s][0][0] : &Bs4[s][0][0];
            #pragma unroll
            for (int dk = 0; dk < 4; dk++) {
                float4 q;
                if (st_half == 0)
                    q = make_float4(vr[dk], vr[8 + dk], vr[4 + dk], vr[12 + dk]);
                else
                    q = make_float4(vr[dk], vr[4 + dk], vr[8 + dk], vr[12 + dk]);
                if (RND) {
                    q.x = totf(q.x); q.y = totf(q.y); q.z = totf(q.z); q.w = totf(q.w);
                }
                base[(st_srow0 + dk) * 66 + st_idx] = q;
            }
        } else {
            #pragma unroll
            for (int j = 0; j < 8; j++) {
                int k = a_kg + j;
                int srow = ((k >> 3) << 2) + (k & 3);
                int comp = (((k >> 2) & 1) << 1) | a_half;
                (&As4[s][srow][a_idx].x)[comp] = RND ? totf(vr[j]) : vr[j];
            }
            int srow = ((b_k >> 3) << 2) + (b_k & 3);
            int comp = (bsel << 1) | ((b_k >> 2) & 1);
            int p0 = (b_n8 >> 4) << 3;
            int x  = (p0 >> 3) & 7;
            #pragma unroll
            for (int j = 0; j < 8; j++) {
                int q = p0 + (j ^ x);
                (&Bs4[s][srow][q].x)[comp] = RND ? totf(vb[j]) : vb[j];
            }
        }
    };

    auto comp = [&](int s) {
        #pragma unroll
        for (int ks = 0; ks < 2; ks++) {
            float4 af[2], bf[4];
            #pragma unroll
            for (int mt = 0; mt < 2; mt++)
                af[mt] = As4[s][ks * 4 + tig][(wm * 2 + mt) * 8 + g];
            #pragma unroll
            for (int np = 0; np < 4; np++) {
                int j = wn * 32 + np * 8 + g;
                bf[np] = Bs4[s][ks * 4 + tig][j ^ ((j >> 3) & 7)];
            }
            #pragma unroll
            for (int mt = 0; mt < 2; mt++)
                #pragma unroll
                for (int np = 0; np < 4; np++) {
                    mma8(acc[mt][2 * np],
                         make_float2(af[mt].x, af[mt].y), make_float2(af[mt].z, af[mt].w),
                         make_float2(bf[np].x, bf[np].y));
                    mma8(acc[mt][2 * np + 1],
                         make_float2(af[mt].x, af[mt].y), make_float2(af[mt].z, af[mt].w),
                         make_float2(bf[np].z, bf[np].w));
                }
        }
    };

    ldg(0); sts(0); __syncthreads();
    for (int t = 0; t < T; t++) {
        if (t + 1 < T) ldg((t + 1) << 4);
        comp(t & 1);
        if (t + 1 < T) { sts((t + 1) & 1); __syncthreads(); }
    }

    // ---------------- epilogue ----------------
    #pragma unroll
    for (int mt = 0; mt < 2; mt++) {
        int mrow = m0 + wm * 32 + mt * 16 + g;
        #pragma unroll
        for (int half = 0; half < 2; half++) {
            int m = mrow + half * 8;
            if (GUARD && m >= M) continue;
            #pragma unroll
            for (int nt = 0; nt < 8; nt++) {
                int n = n0 + wn * 64 + nt * 8 + tig * 2;
                float bv0, bv1;
                if (ADJ) {
                    bv0 = biasp[n]; bv1 = biasp[n + 1];
                } else {
                    bv0 = (n     < nsb) ? bias1[n]     : bias2[n - nsb];
                    bv1 = (n + 1 < nsb) ? bias1[n + 1] : bias2[n + 1 - nsb];
                }
                float v0 = acc[mt][nt][half * 2 + 0] + bv0;
                float v1 = acc[mt][nt][half * 2 + 1] + bv1;
                float2* cp = reinterpret_cast<float2*>(C + (long)m * ldc + n);
                if (EPI == 1) {
                    float2 hv = *reinterpret_cast<const float2*>(A1 + (long)m * lda + n);
                    float2 dv = *reinterpret_cast<const float2*>(A2 + (long)m * lda + n);
                    float a0 = sigm(v0), a1 = sigm(v1);
                    *cp = make_float2(a0 * hv.x + (1.f - a0) * dv.x,
                                      a1 * hv.y + (1.f - a1) * dv.y);
                } else if (ADJ) {
                    *cp = make_float2(totf(v0), totf(v1));
                } else {
                    *cp = make_float2(v0, v1);
                }
            }
        }
    }
}

// ---------------- fused weight rounding (single launch) ----------------
__global__ void wround_k(const float4* w_ih, const float4* w_hh,
                         const float4* W_ein, const float4* W_eout, const float4* W_hn,
                         float4* wih, float4* whh, float4* wein, float4* weout, float4* whn)
{
    const int S0 = 24576, S1 = S0 + 12288, S2 = S1 + 4096, S3 = S2 + 4096, S4 = S3 + 8192;
    for (int i = blockIdx.x * blockDim.x + threadIdx.x; i < S4; i += gridDim.x * blockDim.x) {
        const float4* s; float4* d; int j;
        if      (i < S0) { s = w_ih;   d = wih;   j = i; }
        else if (i < S1) { s = w_hh;   d = whh;   j = i - S0; }
        else if (i < S2) { s = W_ein;  d = wein;  j = i - S1; }
        else if (i < S3) { s = W_eout; d = weout; j = i - S2; }
        else             { s = W_hn;   d = whn;   j = i - S3; }
        float4 v = s[j];
        d[j] = make_float4(totf(v.x), totf(v.y), totf(v.z), totf(v.w));
    }
}

// ---------------- wide gather (rounded) ----------------
__global__ void gather_k(const int* __restrict__ inputs,
                         const float4* __restrict__ emb4,
                         float4* __restrict__ h04, long total4)
{
    long i = (long)blockIdx.x * blockDim.x + threadIdx.x;
    if (i >= total4) return;
    long m = i >> 5;
    int  t = (int)(i & 31);
    float4 v = emb4[(long)inputs[m] * 32 + t];
    h04[i] = make_float4(totf(v.x), totf(v.y), totf(v.z), totf(v.w));
}

__global__ void pool_k(const float* __restrict__ h0,
                       const int* __restrict__ gm,
                       float* __restrict__ star)
{
    int b = blockIdx.x, t = threadIdx.x;
    float s = 0.f, c = 0.f;
    const float* hb = h0 + (long)b * NN * HH;
    const int* gb = gm + b * NN;
    for (int i = 0; i < NN; i++) {
        float gmask = (float)gb[i];
        s += gmask * hb[(long)i * HH + t];
        c += gmask;
    }
    star[b * HH + t] = s / c;
}

// ---------------- wide GRU elementwise ----------------
__global__ void gru_k(const float* __restrict__ gi, const float* __restrict__ gh,
                      const float* __restrict__ h0, float* __restrict__ hout,
                      long total)
{
    long i = (long)blockIdx.x * blockDim.x + threadIdx.x;
    if (i >= total) return;
    long m = i >> 7;
    int  j = (int)(i & 127);
    long base = m * (3 * HH);
    float ir = gi[base + j],         hr = gh[base + j];
    float ii = gi[base + HH + j],    hi = gh[base + HH + j];
    float in_ = gi[base + 2*HH + j], hn = gh[base + 2*HH + j];
    float r  = sigm(ir + hr);
    float ig = sigm(ii + hi);
    float ng = tanhf(in_ + r * hn);
    float h  = h0[i];
    hout[i] = ng + ig * (h - ng);
}

// ---------------- star blend + attention pooling ----------------
__global__ void star_k(float* __restrict__ hidden,
                       const int* __restrict__ gm,
                       const float* __restrict__ star_in,
                       float* __restrict__ star_out)
{
    const float inv_sqrt_h = 0.0883883476483184f;  // 1/sqrt(128)
    int b = blockIdx.x;
    int t = threadIdx.x;
    int lane = t & 31, warp = t >> 5;

    __shared__ float st[HH];
    __shared__ float w[NN];
    __shared__ float red[HH];

    st[t] = star_in[(long)b * HH + t];
    __syncthreads();

    float ssp = 0.f;
    #pragma unroll
    for (int u = 0; u < 4; u++) { float v = st[lane + 32 * u]; ssp += v * v; }
    #pragma unroll
    for (int off = 16; off > 0; off >>= 1) ssp += __shfl_xor_sync(0xffffffffu, ssp, off);
    float ss = ssp;

    float* hb = hidden + (long)b * NN * HH;

    for (int i = warp; i < NN; i += 4) {
        float* hr = hb + (long)i * HH;
        float d = 0.f;
        #pragma unroll
        for (int u = 0; u < 4; u++) d += hr[lane + 32 * u] * st[lane + 32 * u];
        #pragma unroll
        for (int off = 16; off > 0; off >>= 1) d += __shfl_xor_sync(0xffffffffu, d, off);
        float alpha = sigm(d * inv_sqrt_h);
        #pragma unroll
        for (int u = 0; u < 4; u++) {
            int c = lane + 32 * u;
            hr[c] = totf((1.f - alpha) * hr[c] + alpha * st[c]);
        }
        float d2 = (1.f - alpha) * d + alpha * ss;
        if (lane == 0) w[i] = expf(d2) * (float)gm[b * NN + i];
    }
    __syncthreads();

    red[t] = (t < NN) ? w[t] : 0.f;
    __syncthreads();
    for (int s = 64; s > 0; s >>= 1) {
        if (t < s) red[t] += red[t + s];
        __syncthreads();
    }
    float S = red[0] + 1e-24f;

    float acc = 0.f;
    for (int i = 0; i < NN; i++) acc += w[i] * hb[(long)i * HH + t];
    star_out[(long)b * HH + t] = acc / S;
}

// ---------------- launch ----------------
extern "C" void kernel_launch(void* const* d_in, const int* in_sizes, int n_in,
                              void* d_out, int out_size)
{
    const int*   inputs = (const int*)d_in[0];
    const float* A      = (const float*)d_in[1];
    const int*   gm     = (const int*)d_in[2];
    const float* emb    = (const float*)d_in[3];
    const float* w_ih   = (const float*)d_in[4];
    const float* w_hh   = (const float*)d_in[5];
    const float* b_ih   = (const float*)d_in[6];
    const float* b_hh   = (const float*)d_in[7];
    const float* b_iah  = (const float*)d_in[8];
    const float* b_oah  = (const float*)d_in[9];
    const float* W_ein  = (const float*)d_in[10];
    const float* b_ein  = (const float*)d_in[11];
    const float* W_eout = (const float*)d_in[12];
    const float* b_eout = (const float*)d_in[13];
    const float* W_hn   = (const float*)d_in[14];
    const float* b_hn   = (const float*)d_in[15];
    float* out = (float*)d_out;

    float *h0, *e, *inp, *gi, *gh, *hid, *star;
    float *wih, *whh, *wein, *weout, *whn;
    cudaGetSymbolAddress((void**)&h0,    g_h0);
    cudaGetSymbolAddress((void**)&e,     g_e);
    cudaGetSymbolAddress((void**)&inp,   g_inp);
    cudaGetSymbolAddress((void**)&gi,    g_gi);
    cudaGetSymbolAddress((void**)&gh,    g_gh);
    cudaGetSymbolAddress((void**)&hid,   g_hid);
    cudaGetSymbolAddress((void**)&star,  g_star);
    cudaGetSymbolAddress((void**)&wih,   g_wih);
    cudaGetSymbolAddress((void**)&whh,   g_whh);
    cudaGetSymbolAddress((void**)&wein,  g_wein);
    cudaGetSymbolAddress((void**)&weout, g_weout);
    cudaGetSymbolAddress((void**)&whn,   g_whn);

    const long totBNH = (long)MTOT * HH;
    const int BIG = 1 << 30;

    // 0) round all weights (tf32-rna), one launch
    wround_k<<<208, 256>>>((const float4*)w_ih, (const float4*)w_hh,
                           (const float4*)W_ein, (const float4*)W_eout, (const float4*)W_hn,
                           (float4*)wih, (float4*)whh, (float4*)wein, (float4*)weout, (float4*)whn);

    // 1) wide gather (rounded) + initial star
    gather_k<<<(unsigned)((totBNH / 4 + 255) / 256), 256>>>(
        inputs, (const float4*)emb, (float4*)h0, totBNH / 4);
    pool_k<<<BSZ, HH>>>(h0, gm, star);

    // 2) e = [h0 @ W_ein^T + b_ein | h0 @ W_eout^T + b_eout]
    tc_gemm<true, false, 0, false, false, false><<<dim3(2, MTOT / 128), 256>>>(
        h0, h0, 0, HH, 0,
        wein, weout, HH, 0, HH,
        b_ein, b_eout, HH,
        e, 0, 2 * HH,
        MTOT, 2 * HH, HH);

    // 3) both adjacency GEMMs in one launch (z: 0..1023 in-half, 1024..2047 out-half)
    tc_gemm<false, true, 0, false, true, true><<<dim3(1, 1, 2 * BSZ), 256>>>(
        A, A, (long)NN * 2 * NN, 2 * NN, 0,
        e, e, BIG, (long)NN * 2 * HH, 2 * HH,
        b_iah, b_oah, BIG,
        inp, (long)NN * 2 * HH, 2 * HH,
        NN, HH, NN);

    // 4) gi = inp @ w_ih^T + b_ih ; gh = h0 @ w_hh^T + b_hh
    tc_gemm<true, false, 0, false, false, false><<<dim3(3, MTOT / 128), 256>>>(
        inp, inp, 0, 2 * HH, 0,
        wih, wih, BIG, 0, 2 * HH,
        b_ih, b_ih, BIG,
        gi, 0, 3 * HH,
        MTOT, 3 * HH, 2 * HH);
    tc_gemm<true, false, 0, false, false, false><<<dim3(3, MTOT / 128), 256>>>(
        h0, h0, 0, HH, 0,
        whh, whh, BIG, 0, HH,
        b_hh, b_hh, BIG,
        gh, 0, 3 * HH,
        MTOT, 3 * HH, HH);

    // 5) wide GRU elementwise -> hid
    gru_k<<<(unsigned)((totBNH + 255) / 256), 256>>>(gi, gh, h0, hid, totBNH);

    // 6) star blend + attention pooling (rounds hid, final star -> out tail)
    star_k<<<BSZ, HH>>>(hid, gm, star, out + totBNH);

    // 7+8) highway fused: [h0|hid] @ W_hn^T + b_hn (split-K), sigmoid blend -> out
    tc_gemm<true, false, 1, true, false, false><<<dim3(1, MTOT / 128), 256>>>(
        h0, hid, 0, HH, HH,
        whn, whn, BIG, 0, 2 * HH,
        b_hn, b_hn, BIG,
        out, 0, HH,
        MTOT, HH, 2 * HH);
}

// round 14
// speedup vs baseline: 1.1307x; 1.1307x over previous
#include <cuda_runtime.h>
#include <math.h>
#include <stdint.h>

#define BSZ 1024
#define NN  100
#define HH  128
#define MTOT (BSZ * NN)   // 102400

// ---------------- scratch (no allocs allowed) ----------------
__device__ float g_h0[(size_t)MTOT * HH];
__device__ float g_e[(size_t)MTOT * 2 * HH];
__device__ float g_inp[(size_t)MTOT * 2 * HH];
__device__ float g_gi[(size_t)MTOT * 3 * HH];
__device__ float g_gh[(size_t)MTOT * 3 * HH];
__device__ float g_hid[(size_t)MTOT * HH];
__device__ float g_star[(size_t)BSZ * HH];
// tf32-rounded weight copies
__device__ float g_wih[3 * HH * 2 * HH];
__device__ float g_whh[3 * HH * HH];
__device__ float g_wein[HH * HH];
__device__ float g_weout[HH * HH];
__device__ float g_whn[HH * 2 * HH];

// ---------------- helpers ----------------
__device__ __forceinline__ float totf(float x) {
    uint32_t u; asm("cvt.rna.tf32.f32 %0, %1;" : "=r"(u) : "f"(x));
    return __uint_as_float(u);
}
__device__ __forceinline__ float sigm(float x) { return 1.f / (1.f + expf(-x)); }

__device__ __forceinline__ void mma8(float c[4], float2 a01, float2 a23, float2 b01) {
    asm volatile(
        "mma.sync.aligned.m16n8k8.row.col.f32.tf32.tf32.f32 "
        "{%0,%1,%2,%3},{%4,%5,%6,%7},{%8,%9},{%0,%1,%2,%3};"
        : "+f"(c[0]), "+f"(c[1]), "+f"(c[2]), "+f"(c[3])
        : "r"(__float_as_uint(a01.x)), "r"(__float_as_uint(a01.y)),
          "r"(__float_as_uint(a23.x)), "r"(__float_as_uint(a23.y)),
          "r"(__float_as_uint(b01.x)), "r"(__float_as_uint(b01.y)));
}

// ---------------- tensor-core tf32 GEMM (round-11 proven) ----------------
// 256 thr, CTA tile 128x128, warp tile 32x64, BK=16, double buffer, 1 bar/K-step.
// float4-quad SMEM layout: one LDS.128 = one full A fragment / two B fragments.
// A quad (srow=((k>>3)<<2)+(k&3), idx=((m>>4)<<3)+(m&7)):
//   {A[m][k], A[m+8][k], A[m][k+4], A[m+8][k+4]}   comp = ((k>>2)&1)*2 + ((m>>3)&1)
// B quad (same srow, idx q = p ^ ((p>>3)&7), p=((n>>4)<<3)+(n&7)):
//   {B[n][k], B[n][k+4], B[n+8][k], B[n+8][k+4]}   comp = ((n>>3)&1)*2 + ((k>>2)&1)
template<bool BT, bool GUARD, int EPI, bool SPLITK, bool RND, bool ADJ>
__global__ __launch_bounds__(256, 2)
void tc_gemm(const float* __restrict__ A1, const float* __restrict__ A2,
             long sA, int lda, int ksplit,
             const float* __restrict__ B1, const float* __restrict__ B2, int nsB,
             long sB, int ldb,
             const float* __restrict__ bias1, const float* __restrict__ bias2, int nsb,
             float* __restrict__ C, long sC, int ldc,
             int M, int N, int K)
{
    __shared__ float4 As4[2][8][66];
    __shared__ float4 Bs4[2][8][66];

    const long zsel = ADJ ? (long)(blockIdx.z & 1023) : (long)blockIdx.z;
    const int  half_adj = ADJ ? (int)(blockIdx.z >> 10) : 0;

    A1 += zsel * sA + (ADJ ? half_adj * NN : 0);
    C  += zsel * sC + (ADJ ? half_adj * HH : 0);
    const float* biasp = (ADJ && half_adj) ? bias2 : bias1;

    const int m0 = blockIdx.y * 128, n0 = blockIdx.x * 128;
    const int tid = threadIdx.x;
    const int lane = tid & 31, warp = tid >> 5;
    const int wm = warp >> 1, wn = warp & 1;
    const int g = lane >> 2, tig = lane & 3;

    const int a_row = tid >> 1, a_kg = (tid & 1) << 3;
    const float* pA1 = A1 + (long)(m0 + a_row) * lda + a_kg;
    const float* pA2 = SPLITK ? (A2 + (long)(m0 + a_row) * lda + a_kg) : pA1;
    const int a_idx  = ((a_row >> 4) << 3) + (a_row & 7);
    const int a_half = (a_row >> 3) & 1;

    const float* Bp;
    int b_kg = 0, b_k = 0, b_n8 = 0;
    int bq = 0, bsel = 0;
    if (BT) {
        int b_n = tid >> 1; b_kg = (tid & 1) << 3;
        int gn = n0 + b_n;
        const float* Bsel = (gn < nsB) ? (B1 + (long)gn * ldb)
                                       : (B2 + (long)(gn - nsB) * ldb);
        Bp = Bsel + b_kg;
        int p = ((b_n >> 4) << 3) + (b_n & 7);
        bq = p ^ ((p >> 3) & 7);
        bsel = (b_n >> 3) & 1;
    } else {
        b_k = tid >> 4;
        b_n8 = (tid & 15) << 3;
        Bp = B1 + zsel * sB + (ADJ ? half_adj * HH : 0) + (long)b_k * ldb + n0 + b_n8;
        bsel = (b_n8 >> 3) & 1;
    }

    float acc[2][8][4] = {};
    __align__(16) float va[8];
    __align__(16) float vb[8];
    const int T = (K + 15) >> 4;

    auto ldg = [&](int k0) {
        if (!GUARD) {
            const float* p;
            if (SPLITK) {
                int kk = k0 + a_kg;
                p = (kk < ksplit) ? (pA1 + k0) : (pA2 + (k0 - ksplit));
            } else {
                p = pA1 + k0;
            }
            *reinterpret_cast<float4*>(va)     = *reinterpret_cast<const float4*>(p);
            *reinterpret_cast<float4*>(va + 4) = *reinterpret_cast<const float4*>(p + 4);
        } else {
            bool rok = (m0 + a_row) < M;
            if (rok && (k0 + a_kg + 8) <= K) {
                *reinterpret_cast<float4*>(va)     = *reinterpret_cast<const float4*>(pA1 + k0);
                *reinterpret_cast<float4*>(va + 4) = *reinterpret_cast<const float4*>(pA1 + k0 + 4);
            } else {
                #pragma unroll
                for (int j = 0; j < 8; j++)
                    va[j] = (rok && (k0 + a_kg + j) < K) ? pA1[k0 + j] : 0.f;
            }
        }
        if (BT) {
            *reinterpret_cast<float4*>(vb)     = *reinterpret_cast<const float4*>(Bp + k0);
            *reinterpret_cast<float4*>(vb + 4) = *reinterpret_cast<const float4*>(Bp + k0 + 4);
        } else {
            if ((k0 + b_k) < K) {
                const float* bp = Bp + (long)k0 * ldb;
                *reinterpret_cast<float4*>(vb)     = *reinterpret_cast<const float4*>(bp);
                *reinterpret_cast<float4*>(vb + 4) = *reinterpret_cast<const float4*>(bp + 4);
            } else {
                #pragma unroll
                for (int j = 0; j < 8; j++) vb[j] = 0.f;
            }
        }
    };

    auto sts = [&](int s) {
        #pragma unroll
        for (int j = 0; j < 8; j++) {
            int k = a_kg + j;
            int srow = ((k >> 3) << 2) + (k & 3);
            int comp = (((k >> 2) & 1) << 1) | a_half;
            (&As4[s][srow][a_idx].x)[comp] = RND ? totf(va[j]) : va[j];
        }
        if (BT) {
            #pragma unroll
            for (int j = 0; j < 8; j++) {
                int k = b_kg + j;
                int srow = ((k >> 3) << 2) + (k & 3);
                int comp = (bsel << 1) | ((k >> 2) & 1);
                (&Bs4[s][srow][bq].x)[comp] = RND ? totf(vb[j]) : vb[j];
            }
        } else {
            int srow = ((b_k >> 3) << 2) + (b_k & 3);
            int comp = (bsel << 1) | ((b_k >> 2) & 1);
            int p0 = (b_n8 >> 4) << 3;
            int x  = (p0 >> 3) & 7;
            #pragma unroll
            for (int j = 0; j < 8; j++) {
                // value for n = b_n8 + j goes to swizzled slot p0 + (j ^ x)
                int q = p0 + (j ^ x);
                (&Bs4[s][srow][q].x)[comp] = RND ? totf(vb[j]) : vb[j];
            }
        }
    };

    auto comp = [&](int s) {
        #pragma unroll
        for (int ks = 0; ks < 2; ks++) {
            float4 af[2], bf[4];
            #pragma unroll
            for (int mt = 0; mt < 2; mt++)
                af[mt] = As4[s][ks * 4 + tig][(wm * 2 + mt) * 8 + g];
            #pragma unroll
            for (int np = 0; np < 4; np++) {
                int j = wn * 32 + np * 8 + g;
                bf[np] = Bs4[s][ks * 4 + tig][j ^ ((j >> 3) & 7)];
            }
            #pragma unroll
            for (int mt = 0; mt < 2; mt++)
                #pragma unroll
                for (int np = 0; np < 4; np++) {
                    mma8(acc[mt][2 * np],
                         make_float2(af[mt].x, af[mt].y), make_float2(af[mt].z, af[mt].w),
                         make_float2(bf[np].x, bf[np].y));
                    mma8(acc[mt][2 * np + 1],
                         make_float2(af[mt].x, af[mt].y), make_float2(af[mt].z, af[mt].w),
                         make_float2(bf[np].z, bf[np].w));
                }
        }
    };

    ldg(0); sts(0); __syncthreads();
    for (int t = 0; t < T; t++) {
        if (t + 1 < T) ldg((t + 1) << 4);
        comp(t & 1);
        if (t + 1 < T) { sts((t + 1) & 1); __syncthreads(); }
    }

    // ---------------- epilogue ----------------
    #pragma unroll
    for (int mt = 0; mt < 2; mt++) {
        int mrow = m0 + wm * 32 + mt * 16 + g;
        #pragma unroll
        for (int half = 0; half < 2; half++) {
            int m = mrow + half * 8;
            if (GUARD && m >= M) continue;
            #pragma unroll
            for (int nt = 0; nt < 8; nt++) {
                int n = n0 + wn * 64 + nt * 8 + tig * 2;
                float bv0, bv1;
                if (ADJ) {
                    bv0 = biasp[n]; bv1 = biasp[n + 1];
                } else {
                    bv0 = (n     < nsb) ? bias1[n]     : bias2[n - nsb];
                    bv1 = (n + 1 < nsb) ? bias1[n + 1] : bias2[n + 1 - nsb];
                }
                float v0 = acc[mt][nt][half * 2 + 0] + bv0;
                float v1 = acc[mt][nt][half * 2 + 1] + bv1;
                float2* cp = reinterpret_cast<float2*>(C + (long)m * ldc + n);
                if (EPI == 1) {
                    float2 hv = *reinterpret_cast<const float2*>(A1 + (long)m * lda + n);
                    float2 dv = *reinterpret_cast<const float2*>(A2 + (long)m * lda + n);
                    float a0 = sigm(v0), a1 = sigm(v1);
                    *cp = make_float2(a0 * hv.x + (1.f - a0) * dv.x,
                                      a1 * hv.y + (1.f - a1) * dv.y);
                } else if (ADJ) {
                    *cp = make_float2(totf(v0), totf(v1));
                } else {
                    *cp = make_float2(v0, v1);
                }
            }
        }
    }
}

// ---------------- fused weight rounding (single launch) ----------------
__global__ void wround_k(const float4* w_ih, const float4* w_hh,
                         const float4* W_ein, const float4* W_eout, const float4* W_hn,
                         float4* wih, float4* whh, float4* wein, float4* weout, float4* whn)
{
    const int S0 = 24576, S1 = S0 + 12288, S2 = S1 + 4096, S3 = S2 + 4096, S4 = S3 + 8192;
    for (int i = blockIdx.x * blockDim.x + threadIdx.x; i < S4; i += gridDim.x * blockDim.x) {
        const float4* s; float4* d; int j;
        if      (i < S0) { s = w_ih;   d = wih;   j = i; }
        else if (i < S1) { s = w_hh;   d = whh;   j = i - S0; }
        else if (i < S2) { s = W_ein;  d = wein;  j = i - S1; }
        else if (i < S3) { s = W_eout; d = weout; j = i - S2; }
        else             { s = W_hn;   d = whn;   j = i - S3; }
        float4 v = s[j];
        d[j] = make_float4(totf(v.x), totf(v.y), totf(v.z), totf(v.w));
    }
}

// ---------------- wide gather (rounded) ----------------
__global__ void gather_k(const int* __restrict__ inputs,
                         const float4* __restrict__ emb4,
                         float4* __restrict__ h04, long total4)
{
    long i = (long)blockIdx.x * blockDim.x + threadIdx.x;
    if (i >= total4) return;
    long m = i >> 5;
    int  t = (int)(i & 31);
    float4 v = emb4[(long)inputs[m] * 32 + t];
    h04[i] = make_float4(totf(v.x), totf(v.y), totf(v.z), totf(v.w));
}

__global__ void pool_k(const float* __restrict__ h0,
                       const int* __restrict__ gm,
                       float* __restrict__ star)
{
    int b = blockIdx.x, t = threadIdx.x;
    const float* hb = h0 + (long)b * NN * HH;
    const int* gb = gm + b * NN;
    float s0 = 0.f, s1 = 0.f, s2 = 0.f, s3 = 0.f, c = 0.f;
    #pragma unroll 1
    for (int i = 0; i < NN; i += 4) {
        float g0 = (float)gb[i],     g1 = (float)gb[i + 1];
        float g2 = (float)gb[i + 2], g3 = (float)gb[i + 3];
        s0 += g0 * hb[(long)(i    ) * HH + t];
        s1 += g1 * hb[(long)(i + 1) * HH + t];
        s2 += g2 * hb[(long)(i + 2) * HH + t];
        s3 += g3 * hb[(long)(i + 3) * HH + t];
        c += g0 + g1 + g2 + g3;
    }
    star[b * HH + t] = (s0 + s1 + s2 + s3) / c;   // NN = 100 divisible by 4
}

// ---------------- wide GRU elementwise (float4) ----------------
__global__ void gru_k(const float4* __restrict__ gi4, const float4* __restrict__ gh4,
                      const float4* __restrict__ h04, float4* __restrict__ hout4,
                      long total4)
{
    long i = (long)blockIdx.x * blockDim.x + threadIdx.x;
    if (i >= total4) return;
    long m = i >> 5;            // 32 float4 per row
    int  j = (int)(i & 31);
    long base = m * 96;         // 3*128/4 float4 per gate row
    float4 ir = gi4[base + j], ii = gi4[base + 32 + j], in_ = gi4[base + 64 + j];
    float4 hr = gh4[base + j], hi = gh4[base + 32 + j], hn  = gh4[base + 64 + j];
    float4 h  = h04[i];
    float4 o;
    {
        float r  = sigm(ir.x + hr.x);
        float ig = sigm(ii.x + hi.x);
        float ng = tanhf(in_.x + r * hn.x);
        o.x = ng + ig * (h.x - ng);
    }
    {
        float r  = sigm(ir.y + hr.y);
        float ig = sigm(ii.y + hi.y);
        float ng = tanhf(in_.y + r * hn.y);
        o.y = ng + ig * (h.y - ng);
    }
    {
        float r  = sigm(ir.z + hr.z);
        float ig = sigm(ii.z + hi.z);
        float ng = tanhf(in_.z + r * hn.z);
        o.z = ng + ig * (h.z - ng);
    }
    {
        float r  = sigm(ir.w + hr.w);
        float ig = sigm(ii.w + hi.w);
        float ng = tanhf(in_.w + r * hn.w);
        o.w = ng + ig * (h.w - ng);
    }
    hout4[i] = o;
}

// ---------------- star blend + attention pooling ----------------
__global__ void star_k(float* __restrict__ hidden,
                       const int* __restrict__ gm,
                       const float* __restrict__ star_in,
                       float* __restrict__ star_out)
{
    const float inv_sqrt_h = 0.0883883476483184f;  // 1/sqrt(128)
    int b = blockIdx.x;
    int t = threadIdx.x;
    int lane = t & 31, warp = t >> 5;

    __shared__ float st[HH];
    __shared__ float w[NN];
    __shared__ float red[HH];

    st[t] = star_in[(long)b * HH + t];
    __syncthreads();

    float ssp = 0.f;
    #pragma unroll
    for (int u = 0; u < 4; u++) { float v = st[lane + 32 * u]; ssp += v * v; }
    #pragma unroll
    for (int off = 16; off > 0; off >>= 1) ssp += __shfl_xor_sync(0xffffffffu, ssp, off);
    float ss = ssp;

    float* hb = hidden + (long)b * NN * HH;

    for (int i = warp; i < NN; i += 4) {
        float* hr = hb + (long)i * HH;
        float d = 0.f;
        #pragma unroll
        for (int u = 0; u < 4; u++) d += hr[lane + 32 * u] * st[lane + 32 * u];
        #pragma unroll
        for (int off = 16; off > 0; off >>= 1) d += __shfl_xor_sync(0xffffffffu, d, off);
        float alpha = sigm(d * inv_sqrt_h);
        #pragma unroll
        for (int u = 0; u < 4; u++) {
            int c = lane + 32 * u;
            hr[c] = totf((1.f - alpha) * hr[c] + alpha * st[c]);
        }
        float d2 = (1.f - alpha) * d + alpha * ss;
        if (lane == 0) w[i] = expf(d2) * (float)gm[b * NN + i];
    }
    __syncthreads();

    red[t] = (t < NN) ? w[t] : 0.f;
    __syncthreads();
    for (int s = 64; s > 0; s >>= 1) {
        if (t < s) red[t] += red[t + s];
        __syncthreads();
    }
    float S = red[0] + 1e-24f;

    // 4 independent accumulators for MLP (NN = 100 divisible by 4)
    float a0 = 0.f, a1 = 0.f, a2 = 0.f, a3 = 0.f;
    #pragma unroll 1
    for (int i = 0; i < NN; i += 4) {
        a0 += w[i]     * hb[(long)(i    ) * HH + t];
        a1 += w[i + 1] * hb[(long)(i + 1) * HH + t];
        a2 += w[i + 2] * hb[(long)(i + 2) * HH + t];
        a3 += w[i + 3] * hb[(long)(i + 3) * HH + t];
    }
    star_out[(long)b * HH + t] = (a0 + a1 + a2 + a3) / S;
}

// ---------------- launch ----------------
extern "C" void kernel_launch(void* const* d_in, const int* in_sizes, int n_in,
                              void* d_out, int out_size)
{
    const int*   inputs = (const int*)d_in[0];
    const float* A      = (const float*)d_in[1];
    const int*   gm     = (const int*)d_in[2];
    const float* emb    = (const float*)d_in[3];
    const float* w_ih   = (const float*)d_in[4];
    const float* w_hh   = (const float*)d_in[5];
    const float* b_ih   = (const float*)d_in[6];
    const float* b_hh   = (const float*)d_in[7];
    const float* b_iah  = (const float*)d_in[8];
    const float* b_oah  = (const float*)d_in[9];
    const float* W_ein  = (const float*)d_in[10];
    const float* b_ein  = (const float*)d_in[11];
    const float* W_eout = (const float*)d_in[12];
    const float* b_eout = (const float*)d_in[13];
    const float* W_hn   = (const float*)d_in[14];
    const float* b_hn   = (const float*)d_in[15];
    float* out = (float*)d_out;

    float *h0, *e, *inp, *gi, *gh, *hid, *star;
    float *wih, *whh, *wein, *weout, *whn;
    cudaGetSymbolAddress((void**)&h0,    g_h0);
    cudaGetSymbolAddress((void**)&e,     g_e);
    cudaGetSymbolAddress((void**)&inp,   g_inp);
    cudaGetSymbolAddress((void**)&gi,    g_gi);
    cudaGetSymbolAddress((void**)&gh,    g_gh);
    cudaGetSymbolAddress((void**)&hid,   g_hid);
    cudaGetSymbolAddress((void**)&star,  g_star);
    cudaGetSymbolAddress((void**)&wih,   g_wih);
    cudaGetSymbolAddress((void**)&whh,   g_whh);
    cudaGetSymbolAddress((void**)&wein,  g_wein);
    cudaGetSymbolAddress((void**)&weout, g_weout);
    cudaGetSymbolAddress((void**)&whn,   g_whn);

    const long totBNH = (long)MTOT * HH;
    const int BIG = 1 << 30;

    // 0) round all weights (tf32-rna), one launch
    wround_k<<<208, 256>>>((const float4*)w_ih, (const float4*)w_hh,
                           (const float4*)W_ein, (const float4*)W_eout, (const float4*)W_hn,
                           (float4*)wih, (float4*)whh, (float4*)wein, (float4*)weout, (float4*)whn);

    // 1) wide gather (rounded) + initial star
    gather_k<<<(unsigned)((totBNH / 4 + 255) / 256), 256>>>(
        inputs, (const float4*)emb, (float4*)h0, totBNH / 4);
    pool_k<<<BSZ, HH>>>(h0, gm, star);

    // 2) e = [h0 @ W_ein^T + b_ein | h0 @ W_eout^T + b_eout]
    tc_gemm<true, false, 0, false, false, false><<<dim3(2, MTOT / 128), 256>>>(
        h0, h0, 0, HH, 0,
        wein, weout, HH, 0, HH,
        b_ein, b_eout, HH,
        e, 0, 2 * HH,
        MTOT, 2 * HH, HH);

    // 3) both adjacency GEMMs in one launch (z: 0..1023 in-half, 1024..2047 out-half)
    tc_gemm<false, true, 0, false, true, true><<<dim3(1, 1, 2 * BSZ), 256>>>(
        A, A, (long)NN * 2 * NN, 2 * NN, 0,
        e, e, BIG, (long)NN * 2 * HH, 2 * HH,
        b_iah, b_oah, BIG,
        inp, (long)NN * 2 * HH, 2 * HH,
        NN, HH, NN);

    // 4) gi = inp @ w_ih^T + b_ih ; gh = h0 @ w_hh^T + b_hh
    tc_gemm<true, false, 0, false, false, false><<<dim3(3, MTOT / 128), 256>>>(
        inp, inp, 0, 2 * HH, 0,
        wih, wih, BIG, 0, 2 * HH,
        b_ih, b_ih, BIG,
        gi, 0, 3 * HH,
        MTOT, 3 * HH, 2 * HH);
    tc_gemm<true, false, 0, false, false, false><<<dim3(3, MTOT / 128), 256>>>(
        h0, h0, 0, HH, 0,
        whh, whh, BIG, 0, HH,
        b_hh, b_hh, BIG,
        gh, 0, 3 * HH,
        MTOT, 3 * HH, HH);

    // 5) wide GRU elementwise (float4) -> hid
    gru_k<<<(unsigned)((totBNH / 4 + 255) / 256), 256>>>(
        (const float4*)gi, (const float4*)gh, (const float4*)h0,
        (float4*)hid, totBNH / 4);

    // 6) star blend + attention pooling (rounds hid, final star -> out tail)
    star_k<<<BSZ, HH>>>(hid, gm, star, out + totBNH);

    // 7+8) highway fused: [h0|hid] @ W_hn^T + b_hn (split-K), sigmoid blend -> out
    tc_gemm<true, false, 1, true, false, false><<<dim3(1, MTOT / 128), 256>>>(
        h0, hid, 0, HH, HH,
        whn, whn, BIG, 0, 2 * HH,
        b_hn, b_hn, BIG,
        out, 0, HH,
        MTOT, HH, 2 * HH);
}